// round 6
// baseline (speedup 1.0000x reference)
#include <cuda_runtime.h>
#include <cuda_fp16.h>
#include <cstdint>

#define BN    128
#define NN    12000
#define NOMIC 3600
#define NFN   7000
#define FCC   56000
#define EE    57000
#define LL    4
#define LAT   100
#define EPSV  1e-5f

// ---------------- scratch (device globals; no allocation allowed) ----------------
__device__ float  g_xT[NN * BN];          // x transposed [n][b]
__device__ float  g_xe[EE * BN];          // edge state [e][b]  (fp32 residual path)
__device__ __half g_zh[FCC * BN];         // z (pre-sigmoid)  fp16
__device__ __half g_s [FCC * BN];         // s = sigmoid(LN(z))  fp16
__device__ __half g_hfc[FCC * BN];        // hfc  fp16
__device__ float  g_b3cum[LL * EE];       // cumulative b3 sums
__device__ float  g_hraw[LAT * BN];       // gemm1 accumulator [j][b]
__device__ float  g_hT  [LAT * BN];       // elu(h) transposed [k][b]
__device__ float  g_red [2 * BN];         // LN sum/sumsq then mu/rstd
__device__ int    g_fcount[NFN];          // edges per source function
__device__ int2   g_fbucket[NFN * 64];    // CSR buckets: (p, e), cap 64

// ---------------- helpers ----------------
__device__ __forceinline__ float4 ld_half4(const __half* p) {
    union { uint2 u; __half2 h[2]; } v;
    v.u = *reinterpret_cast<const uint2*>(p);
    float2 a = __half22float2(v.h[0]);
    float2 b = __half22float2(v.h[1]);
    return make_float4(a.x, a.y, b.x, b.y);
}
__device__ __forceinline__ void st_half4(__half* p, float4 v) {
    union { uint2 u; __half2 h[2]; } o;
    o.h[0] = __floats2half2_rn(v.x, v.y);
    o.h[1] = __floats2half2_rn(v.z, v.w);
    *reinterpret_cast<uint2*>(p) = o.u;
}
__device__ __forceinline__ float eluf(float v) { return v > 0.f ? v : expm1f(v); }

// ---------------- zero out ----------------
__global__ void zeroOutK(float4* __restrict__ out, int n4) {
    int i = blockIdx.x * blockDim.x + threadIdx.x;
    if (i < n4) out[i] = make_float4(0.f, 0.f, 0.f, 0.f);
}

// ---------------- b3cum + zero small scratch (fused) ----------------
__global__ void prepK(const float* __restrict__ b3) {
    int e = blockIdx.x * blockDim.x + threadIdx.x;
    if (e < LAT * BN) g_hraw[e] = 0.f;
    if (e < 2 * BN)   g_red[e] = 0.f;
    if (e < NFN)      g_fcount[e] = 0;
    if (e >= EE) return;
    float a = 0.f;
    #pragma unroll
    for (int l = 0; l < LL; l++) { a += b3[l * EE + e]; g_b3cum[l * EE + e] = a; }
}

// ---------------- build CSR buckets (p, e) over fe positions ----------------
__global__ void histK(const int* __restrict__ w3rows, const int* __restrict__ w3cols, int P) {
    int p = blockIdx.x * blockDim.x + threadIdx.x;
    if (p >= P) return;
    int fs = __ldg(&w3rows[p * 8]) >> 3;
    int e  = __ldg(&w3cols[p * 8]);
    int pos = atomicAdd(&g_fcount[fs], 1);
    if (pos < 64) g_fbucket[fs * 64 + pos] = make_int2(p, e);
}

// ---------------- transpose x : [b][n] -> [n][b] ----------------
__global__ void transposeK(const float* __restrict__ x) {
    __shared__ float t[32][33];
    int n0 = blockIdx.x * 32, b0 = blockIdx.y * 32;
    for (int i = threadIdx.y; i < 32; i += 8)
        t[i][threadIdx.x] = x[(b0 + i) * NN + n0 + threadIdx.x];
    __syncthreads();
    for (int i = threadIdx.y; i < 32; i += 8)
        g_xT[(n0 + i) * BN + b0 + threadIdx.x] = t[threadIdx.x][i];
}

// ---------------- initial edge gather (float4, omic columns zeroed) ----------------
__global__ void gatherK(const int* __restrict__ src) {
    int i = blockIdx.x * blockDim.x + threadIdx.x;   // i = e*32 + lane
    if (i >= EE * 32) return;
    int e = i >> 5, lane = i & 31;
    int s = src[e];
    float4 v = make_float4(0.f, 0.f, 0.f, 0.f);
    if (s >= NOMIC)
        v = *reinterpret_cast<const float4*>(&g_xT[s * BN + lane * 4]);
    *reinterpret_cast<float4*>(&g_xe[e * BN + lane * 4]) = v;
}

// ---------------- gemm1: h_raw[j][b] += sum_k x[b][k] W1[k][j]  (split-K) ----------------
__global__ void gemm1K(const float* __restrict__ W1) {
    __shared__ float Wsm[240 * 20];
    int jt = blockIdx.x, ks = blockIdx.y;   // 5 x 15
    int t = threadIdx.x;                    // 128
    for (int idx = t; idx < 240 * 20; idx += 128) {
        int k = idx / 20, j = idx % 20;
        Wsm[idx] = W1[(ks * 240 + k) * LAT + jt * 20 + j];
    }
    __syncthreads();
    float acc[20];
    #pragma unroll
    for (int j = 0; j < 20; j++) acc[j] = 0.f;
    int b = t;
    const float* xp = &g_xT[(ks * 240) * BN + b];
    for (int k = 0; k < 240; k++) {
        float xv = xp[k * BN];
        #pragma unroll
        for (int j = 0; j < 20; j++) acc[j] += xv * Wsm[k * 20 + j];
    }
    #pragma unroll
    for (int j = 0; j < 20; j++)
        atomicAdd(&g_hraw[(jt * 20 + j) * BN + b], acc[j]);
}

__global__ void gemm1finK(const float* __restrict__ b_ae1) {
    int i = blockIdx.x * blockDim.x + threadIdx.x;   // 12800
    if (i >= LAT * BN) return;
    int j = i >> 7;
    g_hT[i] = eluf(g_hraw[i] + b_ae1[j]);
}

// ---------------- gemm2: z[j][b] = sum_k h[b][k] W2[k][j] + b2[j], packed f32x2 ----------------
__global__ void __launch_bounds__(128) gemm2K(const float* __restrict__ W2,
                                              const float* __restrict__ b2) {
    __shared__ unsigned long long Wp[100 * 32];   // 25.6KB
    int j0 = blockIdx.x * 64;
    int t = threadIdx.x, b = t;
    for (int idx = t; idx < 100 * 32; idx += 128) {
        int k = idx >> 5, j2 = idx & 31;
        Wp[idx] = *reinterpret_cast<const unsigned long long*>(&W2[(size_t)k * FCC + j0 + 2 * j2]);
    }
    __syncthreads();
    unsigned long long acc[32];
    #pragma unroll
    for (int j2 = 0; j2 < 32; j2++)
        acc[j2] = *reinterpret_cast<const unsigned long long*>(&b2[j0 + 2 * j2]);
    for (int k = 0; k < 100; k++) {
        float hv = g_hT[k * BN + b];
        unsigned int hvi = __float_as_uint(hv);
        unsigned long long hv2;
        asm("mov.b64 %0, {%1,%1};" : "=l"(hv2) : "r"(hvi));
        #pragma unroll
        for (int j2 = 0; j2 < 32; j2++)
            asm("fma.rn.f32x2 %0, %1, %2, %0;" : "+l"(acc[j2]) : "l"(Wp[k * 32 + j2]), "l"(hv2));
    }
    float sum = 0.f, sq = 0.f;
    #pragma unroll
    for (int j2 = 0; j2 < 32; j2++) {
        unsigned int ulo, uhi;
        asm("mov.b64 {%0,%1}, %2;" : "=r"(ulo), "=r"(uhi) : "l"(acc[j2]));
        float lo = __uint_as_float(ulo), hi = __uint_as_float(uhi);
        int row = (j0 + 2 * j2) * BN + b;
        g_zh[row] = __float2half(lo);
        g_zh[row + BN] = __float2half(hi);
        sum += lo + hi;
        sq  += lo * lo + hi * hi;
    }
    atomicAdd(&g_red[b], sum);
    atomicAdd(&g_red[BN + b], sq);
}

__global__ void lnstatsK() {
    int b = threadIdx.x;
    float mu = g_red[b] / (float)FCC;
    float var = g_red[BN + b] / (float)FCC - mu * mu;
    g_red[b] = mu;
    g_red[BN + b] = rsqrtf(var + EPSV);
}

// sigmoid(LN(z)) -> fp16 s, half4 per thread
__global__ void sigK() {
    int i = blockIdx.x * blockDim.x + threadIdx.x;
    if (i >= FCC * 32) return;
    int lane = i & 31;
    float4 z = ld_half4(&g_zh[i * 4]);
    float4 mu = *reinterpret_cast<const float4*>(&g_red[lane * 4]);
    float4 rs = *reinterpret_cast<const float4*>(&g_red[BN + lane * 4]);
    float4 v;
    v.x = 1.f / (1.f + expf(-(z.x - mu.x) * rs.x));
    v.y = 1.f / (1.f + expf(-(z.y - mu.y) * rs.y));
    v.z = 1.f / (1.f + expf(-(z.z - mu.z) * rs.z));
    v.w = 1.f / (1.f + expf(-(z.w - mu.w) * rs.w));
    st_half4(&g_s[i * 4], v);
}

// ---------------- spmm1 + groupLN + s*elu  (warp per function, float4 over b) ----------------
__global__ void __launch_bounds__(256) spmm1K(const float* __restrict__ w1,
                                              const float* __restrict__ b1,
                                              int l) {
    __shared__ float ws[512];
    int t = threadIdx.x;            // 256
    int f0 = blockIdx.x * 8;
    ws[t]       = w1[f0 * 64 + t];
    ws[t + 256] = w1[f0 * 64 + 256 + t];
    __syncthreads();
    int w = t >> 5, lane = t & 31;
    int f = f0 + w;
    const float* wf = &ws[w * 64];
    float bc_l = 0.f;
    if (l > 0 && lane < 8) bc_l = __ldg(&g_b3cum[(l - 1) * EE + 8 * f + lane]);
    float4 a[8];
    #pragma unroll
    for (int c = 0; c < 8; c++) {
        float bv = __ldg(&b1[f * 8 + c]);
        a[c] = make_float4(bv, bv, bv, bv);
    }
    #pragma unroll
    for (int j = 0; j < 8; j++) {
        int e = 8 * f + j;
        float4 xv = *reinterpret_cast<const float4*>(&g_xe[e * BN + lane * 4]);
        float bc = __shfl_sync(0xffffffffu, bc_l, j);
        xv.x += bc; xv.y += bc; xv.z += bc; xv.w += bc;
        #pragma unroll
        for (int c = 0; c < 8; c++) {
            float wv = wf[j * 8 + c];
            a[c].x += xv.x * wv; a[c].y += xv.y * wv;
            a[c].z += xv.z * wv; a[c].w += xv.w * wv;
        }
    }
    float4 mu = make_float4(0.f, 0.f, 0.f, 0.f);
    #pragma unroll
    for (int c = 0; c < 8; c++) { mu.x += a[c].x; mu.y += a[c].y; mu.z += a[c].z; mu.w += a[c].w; }
    mu.x *= 0.125f; mu.y *= 0.125f; mu.z *= 0.125f; mu.w *= 0.125f;
    float4 var = make_float4(0.f, 0.f, 0.f, 0.f);
    #pragma unroll
    for (int c = 0; c < 8; c++) {
        float dx = a[c].x - mu.x, dy = a[c].y - mu.y, dz = a[c].z - mu.z, dw = a[c].w - mu.w;
        var.x += dx * dx; var.y += dy * dy; var.z += dz * dz; var.w += dw * dw;
    }
    float4 rs;
    rs.x = rsqrtf(var.x * 0.125f + EPSV);
    rs.y = rsqrtf(var.y * 0.125f + EPSV);
    rs.z = rsqrtf(var.z * 0.125f + EPSV);
    rs.w = rsqrtf(var.w * 0.125f + EPSV);
    #pragma unroll
    for (int c = 0; c < 8; c++) {
        int row = f * 8 + c;
        float4 sv = ld_half4(&g_s[row * BN + lane * 4]);
        float4 v;
        v.x = eluf((a[c].x - mu.x) * rs.x * sv.x);
        v.y = eluf((a[c].y - mu.y) * rs.y * sv.y);
        v.z = eluf((a[c].z - mu.z) * rs.z * sv.z);
        v.w = eluf((a[c].w - mu.w) * rs.w * sv.w);
        st_half4(&g_hfc[row * BN + lane * 4], v);
    }
}

// ---------------- spmm3 v3: block per source function, smem hfc, warps split edges ----------------
__global__ void __launch_bounds__(256) spmm3K(const float* __restrict__ w3) {
    __shared__ __half sh[8 * BN];   // 2 KB: this function's hfc rows
    __shared__ int2 spe[64];
    int fs = blockIdx.x;
    int cnt = g_fcount[fs];
    if (cnt > 64) cnt = 64;
    if (cnt == 0) return;
    int t = threadIdx.x;
    // stage hfc (2048 B, one uint2 per thread) and bucket entries
    reinterpret_cast<uint2*>(sh)[t] =
        reinterpret_cast<const uint2*>(&g_hfc[(size_t)fs * 8 * BN])[t];
    if (t < cnt) spe[t] = g_fbucket[fs * 64 + t];
    __syncthreads();
    int w = t >> 5, lane = t & 31;
    float4 hv[8];
    #pragma unroll
    for (int c = 0; c < 8; c++)
        hv[c] = ld_half4(&sh[c * BN + lane * 4]);
    for (int i = w; i < cnt; i += 8) {
        int p = spe[i].x, e = spe[i].y;
        float4 w0  = *reinterpret_cast<const float4*>(&w3[p * 8]);
        float4 w1v = *reinterpret_cast<const float4*>(&w3[p * 8 + 4]);
        float* xp = &g_xe[(size_t)e * BN + lane * 4];
        float4 acc = *reinterpret_cast<const float4*>(xp);
        acc.x += hv[0].x * w0.x + hv[1].x * w0.y + hv[2].x * w0.z + hv[3].x * w0.w
               + hv[4].x * w1v.x + hv[5].x * w1v.y + hv[6].x * w1v.z + hv[7].x * w1v.w;
        acc.y += hv[0].y * w0.x + hv[1].y * w0.y + hv[2].y * w0.z + hv[3].y * w0.w
               + hv[4].y * w1v.x + hv[5].y * w1v.y + hv[6].y * w1v.z + hv[7].y * w1v.w;
        acc.z += hv[0].z * w0.x + hv[1].z * w0.y + hv[2].z * w0.z + hv[3].z * w0.w
               + hv[4].z * w1v.x + hv[5].z * w1v.y + hv[6].z * w1v.z + hv[7].z * w1v.w;
        acc.w += hv[0].w * w0.x + hv[1].w * w0.y + hv[2].w * w0.z + hv[3].w * w0.w
               + hv[4].w * w1v.x + hv[5].w * w1v.y + hv[6].w * w1v.z + hv[7].w * w1v.w;
        *reinterpret_cast<float4*>(xp) = acc;
    }
}

// ---------------- final: only out-edges survive the mask ----------------
__global__ void finalK(const int* __restrict__ dst, float* __restrict__ out) {
    int i = blockIdx.x * blockDim.x + threadIdx.x;   // 1000*128
    if (i >= 1000 * BN) return;
    int k = i >> 7, b = i & 127;
    int e = FCC + k;
    float v = (g_xe[e * BN + b] + g_b3cum[3 * EE + e]) * 0.25f;
    out[b * NN + dst[e]] = v;
}

// ---------------- launch ----------------
extern "C" void kernel_launch(void* const* d_in, const int* in_sizes, int n_in,
                              void* d_out, int out_size) {
    const float* x       = (const float*)d_in[0];
    const float* W_ae1   = (const float*)d_in[1];
    const float* b_ae1   = (const float*)d_in[2];
    const float* W_ae2   = (const float*)d_in[3];
    const float* b_ae2   = (const float*)d_in[4];
    const float* w1_vals = (const float*)d_in[5];
    const float* b1      = (const float*)d_in[6];
    const float* w3_vals = (const float*)d_in[7];
    const float* b3      = (const float*)d_in[8];
    const int*   src     = (const int*)  d_in[9];
    const int*   dst     = (const int*)  d_in[10];
    const int*   w3_rows = (const int*)  d_in[13];
    const int*   w3_cols = (const int*)  d_in[14];
    float* out = (float*)d_out;

    int nnz1 = in_sizes[5] / LL;
    int nnz3 = in_sizes[7] / LL;
    int P = nnz3 / 8;

    zeroOutK<<<(out_size / 4 + 255) / 256, 256>>>((float4*)out, out_size / 4);
    prepK<<<(EE + 255) / 256, 256>>>(b3);
    histK<<<(P + 255) / 256, 256>>>(w3_rows, w3_cols, P);
    transposeK<<<dim3(NN / 32, BN / 32), dim3(32, 8)>>>(x);
    gatherK<<<(EE * 32 + 255) / 256, 256>>>(src);

    gemm1K<<<dim3(5, 15), 128>>>(W_ae1);
    gemm1finK<<<(LAT * BN + 127) / 128, 128>>>(b_ae1);
    gemm2K<<<FCC / 64, 128>>>(W_ae2, b_ae2);
    lnstatsK<<<1, BN>>>();
    sigK<<<(FCC * 32 + 255) / 256, 256>>>();

    for (int l = 0; l < LL; l++) {
        spmm1K<<<NFN / 8, 256>>>(w1_vals + (size_t)l * nnz1, b1 + (size_t)l * FCC, l);
        spmm3K<<<NFN, 256>>>(w3_vals + (size_t)l * nnz3);
    }

    finalK<<<(1000 * BN) / 256, 256>>>(dst, out);
}

// round 7
// speedup vs baseline: 1.1779x; 1.1779x over previous
#include <cuda_runtime.h>
#include <cuda_fp16.h>
#include <cstdint>

#define BN    128
#define NN    12000
#define NOMIC 3600
#define NFN   7000
#define FCC   56000
#define EE    57000
#define LL    4
#define LAT   100
#define EPSV  1e-5f

// ---------------- scratch (device globals; no allocation allowed) ----------------
__device__ float  g_xT[NN * BN];          // x transposed [n][b]
__device__ float  g_xe[EE * BN];          // edge state [e][b]  (fp32 residual path)
__device__ __half g_zh[FCC * BN];         // z (pre-sigmoid) fp16
__device__ __half g_s [FCC * BN];         // s = sigmoid(LN(z))  fp16
__device__ __half g_hfc[FCC * BN];        // hfc  fp16
__device__ float  g_b3cum[LL * EE];       // cumulative b3 sums
__device__ float  g_hraw[LAT * BN];       // gemm1 accumulator [j][b]
__device__ float  g_hT  [LAT * BN];       // elu(h) transposed [k][b]
__device__ float  g_red [2 * BN];         // LN sum/sumsq then mu/rstd

// ---------------- helpers ----------------
__device__ __forceinline__ float4 ld_half4(const __half* p) {
    union { uint2 u; __half2 h[2]; } v;
    v.u = *reinterpret_cast<const uint2*>(p);
    float2 a = __half22float2(v.h[0]);
    float2 b = __half22float2(v.h[1]);
    return make_float4(a.x, a.y, b.x, b.y);
}
__device__ __forceinline__ void st_half4(__half* p, float4 v) {
    union { uint2 u; __half2 h[2]; } o;
    o.h[0] = __floats2half2_rn(v.x, v.y);
    o.h[1] = __floats2half2_rn(v.z, v.w);
    *reinterpret_cast<uint2*>(p) = o.u;
}
__device__ __forceinline__ float eluf(float v) { return v > 0.f ? v : expm1f(v); }

// ---------------- zero out ----------------
__global__ void zeroOutK(float4* __restrict__ out, int n4) {
    int i = blockIdx.x * blockDim.x + threadIdx.x;
    if (i < n4) out[i] = make_float4(0.f, 0.f, 0.f, 0.f);
}

// ---------------- b3cum + zero small scratch (fused) ----------------
__global__ void prepK(const float* __restrict__ b3) {
    int e = blockIdx.x * blockDim.x + threadIdx.x;
    if (e < LAT * BN) g_hraw[e] = 0.f;
    if (e < 2 * BN)   g_red[e] = 0.f;
    if (e >= EE) return;
    float a = 0.f;
    #pragma unroll
    for (int l = 0; l < LL; l++) { a += b3[l * EE + e]; g_b3cum[l * EE + e] = a; }
}

// ---------------- transpose x : [b][n] -> [n][b] ----------------
__global__ void transposeK(const float* __restrict__ x) {
    __shared__ float t[32][33];
    int n0 = blockIdx.x * 32, b0 = blockIdx.y * 32;
    for (int i = threadIdx.y; i < 32; i += 8)
        t[i][threadIdx.x] = x[(b0 + i) * NN + n0 + threadIdx.x];
    __syncthreads();
    for (int i = threadIdx.y; i < 32; i += 8)
        g_xT[(n0 + i) * BN + b0 + threadIdx.x] = t[threadIdx.x][i];
}

// ---------------- initial edge gather (float4, omic columns zeroed) ----------------
__global__ void gatherK(const int* __restrict__ src) {
    int i = blockIdx.x * blockDim.x + threadIdx.x;   // i = e*32 + lane
    if (i >= EE * 32) return;
    int e = i >> 5, lane = i & 31;
    int s = src[e];
    float4 v = make_float4(0.f, 0.f, 0.f, 0.f);
    if (s >= NOMIC)
        v = *reinterpret_cast<const float4*>(&g_xT[s * BN + lane * 4]);
    *reinterpret_cast<float4*>(&g_xe[e * BN + lane * 4]) = v;
}

// ---------------- gemm1: h_raw[j][b] += sum_k x[b][k] W1[k][j]  (split-K) ----------------
__global__ void gemm1K(const float* __restrict__ W1) {
    __shared__ float Wsm[240 * 20];
    int jt = blockIdx.x, ks = blockIdx.y;   // 5 x 15
    int t = threadIdx.x;                    // 128
    for (int idx = t; idx < 240 * 20; idx += 128) {
        int k = idx / 20, j = idx % 20;
        Wsm[idx] = W1[(ks * 240 + k) * LAT + jt * 20 + j];
    }
    __syncthreads();
    float acc[20];
    #pragma unroll
    for (int j = 0; j < 20; j++) acc[j] = 0.f;
    int b = t;
    const float* xp = &g_xT[(ks * 240) * BN + b];
    for (int k = 0; k < 240; k++) {
        float xv = xp[k * BN];
        #pragma unroll
        for (int j = 0; j < 20; j++) acc[j] += xv * Wsm[k * 20 + j];
    }
    #pragma unroll
    for (int j = 0; j < 20; j++)
        atomicAdd(&g_hraw[(jt * 20 + j) * BN + b], acc[j]);
}

__global__ void gemm1finK(const float* __restrict__ b_ae1) {
    int i = blockIdx.x * blockDim.x + threadIdx.x;   // 12800
    if (i >= LAT * BN) return;
    int j = i >> 7;
    g_hT[i] = eluf(g_hraw[i] + b_ae1[j]);
}

// ---------------- gemm2: z[j][b] = sum_k h[b][k] W2[k][j] + b2[j], packed f32x2 ----------------
__global__ void __launch_bounds__(128) gemm2K(const float* __restrict__ W2,
                                              const float* __restrict__ b2) {
    __shared__ unsigned long long Wp[100 * 32];   // 25.6KB
    int j0 = blockIdx.x * 64;
    int t = threadIdx.x, b = t;
    for (int idx = t; idx < 100 * 32; idx += 128) {
        int k = idx >> 5, j2 = idx & 31;
        Wp[idx] = *reinterpret_cast<const unsigned long long*>(&W2[(size_t)k * FCC + j0 + 2 * j2]);
    }
    __syncthreads();
    unsigned long long acc[32];
    #pragma unroll
    for (int j2 = 0; j2 < 32; j2++)
        acc[j2] = *reinterpret_cast<const unsigned long long*>(&b2[j0 + 2 * j2]);
    unsigned int wbase = (unsigned int)__cvta_generic_to_shared(Wp);
    for (int k = 0; k < 100; k++) {
        float hv = g_hT[k * BN + b];
        unsigned int hvi = __float_as_uint(hv);
        unsigned long long hv2;
        asm("mov.b64 %0, {%1,%1};" : "=l"(hv2) : "r"(hvi));
        #pragma unroll
        for (int j2 = 0; j2 < 32; j2 += 2) {
            unsigned long long w0, w1;
            asm("ld.shared.v2.b64 {%0,%1}, [%2];"
                : "=l"(w0), "=l"(w1) : "r"(wbase + (k * 32 + j2) * 8));
            asm("fma.rn.f32x2 %0, %1, %2, %0;" : "+l"(acc[j2])     : "l"(w0), "l"(hv2));
            asm("fma.rn.f32x2 %0, %1, %2, %0;" : "+l"(acc[j2 + 1]) : "l"(w1), "l"(hv2));
        }
    }
    float sum = 0.f, sq = 0.f;
    #pragma unroll
    for (int j2 = 0; j2 < 32; j2++) {
        unsigned int ulo, uhi;
        asm("mov.b64 {%0,%1}, %2;" : "=r"(ulo), "=r"(uhi) : "l"(acc[j2]));
        float lo = __uint_as_float(ulo), hi = __uint_as_float(uhi);
        int row = (j0 + 2 * j2) * BN + b;
        g_zh[row] = __float2half(lo);
        g_zh[row + BN] = __float2half(hi);
        sum += lo + hi;
        sq  += lo * lo + hi * hi;
    }
    atomicAdd(&g_red[b], sum);
    atomicAdd(&g_red[BN + b], sq);
}

__global__ void lnstatsK() {
    int b = threadIdx.x;
    float mu = g_red[b] / (float)FCC;
    float var = g_red[BN + b] / (float)FCC - mu * mu;
    g_red[b] = mu;
    g_red[BN + b] = rsqrtf(var + EPSV);
}

// sigmoid(LN(z)) -> fp16 s, 4 elems per thread
__global__ void sigK() {
    int i = blockIdx.x * blockDim.x + threadIdx.x;
    if (i >= FCC * 32) return;
    int lane = i & 31;
    float4 z = ld_half4(&g_zh[i * 4]);
    float4 mu = *reinterpret_cast<const float4*>(&g_red[lane * 4]);
    float4 rs = *reinterpret_cast<const float4*>(&g_red[BN + lane * 4]);
    float4 v;
    v.x = 1.f / (1.f + __expf(-(z.x - mu.x) * rs.x));
    v.y = 1.f / (1.f + __expf(-(z.y - mu.y) * rs.y));
    v.z = 1.f / (1.f + __expf(-(z.z - mu.z) * rs.z));
    v.w = 1.f / (1.f + __expf(-(z.w - mu.w) * rs.w));
    st_half4(&g_s[i * 4], v);
}

// ---------------- spmm1 + groupLN + s*elu  (warp per function, float4 over b) ----------------
__global__ void __launch_bounds__(256) spmm1K(const float* __restrict__ w1,
                                              const float* __restrict__ b1,
                                              int l) {
    __shared__ float ws[512];
    int t = threadIdx.x;            // 256
    int f0 = blockIdx.x * 8;
    ws[t]       = w1[f0 * 64 + t];
    ws[t + 256] = w1[f0 * 64 + 256 + t];
    __syncthreads();
    int w = t >> 5, lane = t & 31;
    int f = f0 + w;
    const float* wf = &ws[w * 64];
    float bc_l = 0.f;
    if (l > 0 && lane < 8) bc_l = __ldg(&g_b3cum[(l - 1) * EE + 8 * f + lane]);
    float4 a[8];
    #pragma unroll
    for (int c = 0; c < 8; c++) {
        float bv = __ldg(&b1[f * 8 + c]);
        a[c] = make_float4(bv, bv, bv, bv);
    }
    #pragma unroll
    for (int j = 0; j < 8; j++) {
        int e = 8 * f + j;
        float4 xv = *reinterpret_cast<const float4*>(&g_xe[e * BN + lane * 4]);
        float bc = __shfl_sync(0xffffffffu, bc_l, j);
        xv.x += bc; xv.y += bc; xv.z += bc; xv.w += bc;
        #pragma unroll
        for (int c = 0; c < 8; c++) {
            float wv = wf[j * 8 + c];
            a[c].x += xv.x * wv; a[c].y += xv.y * wv;
            a[c].z += xv.z * wv; a[c].w += xv.w * wv;
        }
    }
    float4 mu = make_float4(0.f, 0.f, 0.f, 0.f);
    #pragma unroll
    for (int c = 0; c < 8; c++) { mu.x += a[c].x; mu.y += a[c].y; mu.z += a[c].z; mu.w += a[c].w; }
    mu.x *= 0.125f; mu.y *= 0.125f; mu.z *= 0.125f; mu.w *= 0.125f;
    float4 var = make_float4(0.f, 0.f, 0.f, 0.f);
    #pragma unroll
    for (int c = 0; c < 8; c++) {
        float dx = a[c].x - mu.x, dy = a[c].y - mu.y, dz = a[c].z - mu.z, dw = a[c].w - mu.w;
        var.x += dx * dx; var.y += dy * dy; var.z += dz * dz; var.w += dw * dw;
    }
    float4 rs;
    rs.x = rsqrtf(var.x * 0.125f + EPSV);
    rs.y = rsqrtf(var.y * 0.125f + EPSV);
    rs.z = rsqrtf(var.z * 0.125f + EPSV);
    rs.w = rsqrtf(var.w * 0.125f + EPSV);
    #pragma unroll
    for (int c = 0; c < 8; c++) {
        int row = f * 8 + c;
        float4 sv = ld_half4(&g_s[row * BN + lane * 4]);
        float4 v;
        v.x = eluf((a[c].x - mu.x) * rs.x * sv.x);
        v.y = eluf((a[c].y - mu.y) * rs.y * sv.y);
        v.z = eluf((a[c].z - mu.z) * rs.z * sv.z);
        v.w = eluf((a[c].w - mu.w) * rs.w * sv.w);
        st_half4(&g_hfc[row * BN + lane * 4], v);
    }
}

// ---------------- spmm3 (warp per fe-edge, fully parallel, float4 xe RMW) ----------------
__global__ void __launch_bounds__(256) spmm3K(const float* __restrict__ w3,
                                              const int* __restrict__ w3rows,
                                              const int* __restrict__ w3cols,
                                              int P) {
    int idx = blockIdx.x * blockDim.x + threadIdx.x;
    int p = idx >> 5, lane = idx & 31;
    if (p >= P) return;
    int fs = __ldg(&w3rows[p * 8]) >> 3;     // source function
    int e  = __ldg(&w3cols[p * 8]);          // unique destination edge
    float4 w0  = *reinterpret_cast<const float4*>(&w3[p * 8]);
    float4 w1v = *reinterpret_cast<const float4*>(&w3[p * 8 + 4]);
    float* xp = &g_xe[(size_t)e * BN + lane * 4];
    float4 acc = *reinterpret_cast<const float4*>(xp);
    const __half* hb = &g_hfc[(size_t)(fs * 8) * BN + lane * 4];
    float4 hv[8];
    #pragma unroll
    for (int c = 0; c < 8; c++) hv[c] = ld_half4(hb + (size_t)c * BN);
    acc.x += hv[0].x * w0.x + hv[1].x * w0.y + hv[2].x * w0.z + hv[3].x * w0.w
           + hv[4].x * w1v.x + hv[5].x * w1v.y + hv[6].x * w1v.z + hv[7].x * w1v.w;
    acc.y += hv[0].y * w0.x + hv[1].y * w0.y + hv[2].y * w0.z + hv[3].y * w0.w
           + hv[4].y * w1v.x + hv[5].y * w1v.y + hv[6].y * w1v.z + hv[7].y * w1v.w;
    acc.z += hv[0].z * w0.x + hv[1].z * w0.y + hv[2].z * w0.z + hv[3].z * w0.w
           + hv[4].z * w1v.x + hv[5].z * w1v.y + hv[6].z * w1v.z + hv[7].z * w1v.w;
    acc.w += hv[0].w * w0.x + hv[1].w * w0.y + hv[2].w * w0.z + hv[3].w * w0.w
           + hv[4].w * w1v.x + hv[5].w * w1v.y + hv[6].w * w1v.z + hv[7].w * w1v.w;
    *reinterpret_cast<float4*>(xp) = acc;
}

// ---------------- final: only out-edges survive the mask ----------------
__global__ void finalK(const int* __restrict__ dst, float* __restrict__ out) {
    int i = blockIdx.x * blockDim.x + threadIdx.x;   // 1000*128
    if (i >= 1000 * BN) return;
    int k = i >> 7, b = i & 127;
    int e = FCC + k;
    float v = (g_xe[e * BN + b] + g_b3cum[3 * EE + e]) * 0.25f;
    out[b * NN + dst[e]] = v;
}

// ---------------- launch ----------------
extern "C" void kernel_launch(void* const* d_in, const int* in_sizes, int n_in,
                              void* d_out, int out_size) {
    const float* x       = (const float*)d_in[0];
    const float* W_ae1   = (const float*)d_in[1];
    const float* b_ae1   = (const float*)d_in[2];
    const float* W_ae2   = (const float*)d_in[3];
    const float* b_ae2   = (const float*)d_in[4];
    const float* w1_vals = (const float*)d_in[5];
    const float* b1      = (const float*)d_in[6];
    const float* w3_vals = (const float*)d_in[7];
    const float* b3      = (const float*)d_in[8];
    const int*   src     = (const int*)  d_in[9];
    const int*   dst     = (const int*)  d_in[10];
    const int*   w3_rows = (const int*)  d_in[13];
    const int*   w3_cols = (const int*)  d_in[14];
    float* out = (float*)d_out;

    int nnz1 = in_sizes[5] / LL;
    int nnz3 = in_sizes[7] / LL;
    int P = nnz3 / 8;

    zeroOutK<<<(out_size / 4 + 255) / 256, 256>>>((float4*)out, out_size / 4);
    prepK<<<(EE + 255) / 256, 256>>>(b3);
    transposeK<<<dim3(NN / 32, BN / 32), dim3(32, 8)>>>(x);
    gatherK<<<(EE * 32 + 255) / 256, 256>>>(src);

    gemm1K<<<dim3(5, 15), 128>>>(W_ae1);
    gemm1finK<<<(LAT * BN + 127) / 128, 128>>>(b_ae1);
    gemm2K<<<FCC / 64, 128>>>(W_ae2, b_ae2);
    lnstatsK<<<1, BN>>>();
    sigK<<<(FCC * 32 + 255) / 256, 256>>>();

    for (int l = 0; l < LL; l++) {
        spmm1K<<<NFN / 8, 256>>>(w1_vals + (size_t)l * nnz1, b1 + (size_t)l * FCC, l);
        spmm3K<<<(P * 32 + 255) / 256, 256>>>(w3_vals + (size_t)l * nnz3, w3_rows, w3_cols, P);
    }

    finalK<<<(1000 * BN) / 256, 256>>>(dst, out);
}